// round 1
// baseline (speedup 1.0000x reference)
#include <cuda_runtime.h>
#include <math.h>

#define Bb 2
#define Tt 1024
#define Dd 768
#define Hh 3072
#define Ee 8
#define Kk 2
#define Nn (Bb*Tt)      // 2048 tokens
#define NK (Nn*Kk)      // 4096 (token, expert) assignments

// ---------------- scratch (device globals; no allocation allowed) ----------
__device__ float g_h[(size_t)NK * Hh];     // gelu(x @ W1[e]) per slot  (~50 MB)
__device__ float g_y[(size_t)NK * Dd];     // h @ W2[e] per slot        (~12.6 MB)
__device__ int   g_counts[Ee];
__device__ int   g_offsets[Ee + 1];
__device__ int   g_topi[NK];
__device__ float g_topw[NK];
__device__ int   g_pos[NK];
__device__ int   g_slot_tok[NK];           // slot -> token
__device__ int   g_tok_slot[NK];           // (token,k) -> slot
__device__ float g_probsum[Ee];

// ---------------- tiny setup kernels ---------------------------------------
__global__ void init_kernel() {
    int t = threadIdx.x;
    if (t < Ee) { g_counts[t] = 0; g_probsum[t] = 0.f; }
}

// one block (128 threads) per token: z3 = x . Wr rows, trigram logits,
// softmax, top-2, gate normalization, expert counting.
__global__ void routing_kernel(const float* __restrict__ x,
                               const float* __restrict__ Wr) {
    int n = blockIdx.x;
    int t = threadIdx.x;
    const float* xr = x + (size_t)n * Dd;
    float a0 = 0.f, a1 = 0.f, a2 = 0.f;
    for (int d = t; d < Dd; d += 128) {
        float xv = xr[d];
        a0 += xv * Wr[d];
        a1 += xv * Wr[Dd + d];
        a2 += xv * Wr[2 * Dd + d];
    }
    __shared__ float s0[128], s1[128], s2[128];
    s0[t] = a0; s1[t] = a1; s2[t] = a2;
    __syncthreads();
    for (int off = 64; off > 0; off >>= 1) {
        if (t < off) { s0[t] += s0[t+off]; s1[t] += s1[t+off]; s2[t] += s2[t+off]; }
        __syncthreads();
    }
    if (t == 0) {
        float z0 = s0[0], z1 = s1[0], z2 = s2[0];
        const float inv3 = 0.57735026918962576f;  // 1/sqrt(3)
        float logits[Ee];
        #pragma unroll
        for (int e = 0; e < Ee; e++) {
            float d0 = (e & 4) ? 1.f : -1.f;   // itertools.product([-1,1],repeat=3)
            float d1 = (e & 2) ? 1.f : -1.f;
            float d2 = (e & 1) ? 1.f : -1.f;
            logits[e] = (d0 * z0 + d1 * z1 + d2 * z2) * inv3;
        }
        float m = logits[0];
        #pragma unroll
        for (int e = 1; e < Ee; e++) m = fmaxf(m, logits[e]);
        float p[Ee]; float sum = 0.f;
        #pragma unroll
        for (int e = 0; e < Ee; e++) { p[e] = expf(logits[e] - m); sum += p[e]; }
        float invs = 1.f / sum;
        #pragma unroll
        for (int e = 0; e < Ee; e++) atomicAdd(&g_probsum[e], p[e] * invs);
        // top-2 (strict > keeps lowest index on ties, matching lax.top_k)
        int i0 = 0;
        #pragma unroll
        for (int e = 1; e < Ee; e++) if (p[e] > p[i0]) i0 = e;
        int i1 = (i0 == 0) ? 1 : 0;
        #pragma unroll
        for (int e = 0; e < Ee; e++) {
            if (e != i0 && p[e] > p[i1]) i1 = e;
        }
        float v0 = p[i0], v1 = p[i1];
        float wd = 1.f / (v0 + v1);
        g_topi[n*2]   = i0; g_topi[n*2+1] = i1;
        g_topw[n*2]   = v0 * wd; g_topw[n*2+1] = v1 * wd;
        g_pos[n*2]    = atomicAdd(&g_counts[i0], 1);
        g_pos[n*2+1]  = atomicAdd(&g_counts[i1], 1);
    }
}

__global__ void offsets_kernel() {
    if (threadIdx.x == 0 && blockIdx.x == 0) {
        int s = 0;
        for (int e = 0; e < Ee; e++) { g_offsets[e] = s; s += g_counts[e]; }
        g_offsets[Ee] = s;
    }
}

__global__ void fill_kernel() {
    int idx = blockIdx.x * 256 + threadIdx.x;
    if (idx >= NK) return;
    int e = g_topi[idx];
    int slot = g_offsets[e] + g_pos[idx];
    g_slot_tok[slot] = idx >> 1;
    g_tok_slot[idx]  = slot;
}

// ---------------- expert GEMMs (fp32 SIMT tiled, 64x64x16, 4x4/thread) -----
#define BM 64
#define BN 64
#define BK 16

// h[slot, :] = gelu( x[token(slot), :] @ W1[e] )
__global__ void gemm1_kernel(const float* __restrict__ x,
                             const float* __restrict__ W1) {
    int e = blockIdx.z;
    int cnt = g_counts[e];
    int m0 = blockIdx.y * BM;
    if (m0 >= cnt) return;
    int n0 = blockIdx.x * BN;
    int base = g_offsets[e] + m0;
    int rows = min(BM, cnt - m0);
    const float* Bw = W1 + (size_t)e * Dd * Hh;

    __shared__ float As[BK][BM];
    __shared__ float Bs[BK][BN];
    __shared__ int   stok[BM];
    int t = threadIdx.x;            // 256 threads
    if (t < BM) stok[t] = (t < rows) ? g_slot_tok[base + t] : -1;
    __syncthreads();

    float acc[4][4] = {};
    int tx = t & 15, ty = t >> 4;

    for (int k0 = 0; k0 < Dd; k0 += BK) {
        #pragma unroll
        for (int i = 0; i < 4; i++) {
            int idx = t + i * 256;
            int m = idx >> 4, kk = idx & 15;
            int tok = stok[m];
            As[kk][m] = (tok >= 0) ? x[(size_t)tok * Dd + k0 + kk] : 0.f;
        }
        #pragma unroll
        for (int i = 0; i < 4; i++) {
            int idx = t + i * 256;
            int kk = idx >> 6, nn = idx & 63;
            Bs[kk][nn] = Bw[(size_t)(k0 + kk) * Hh + n0 + nn];
        }
        __syncthreads();
        #pragma unroll
        for (int kk = 0; kk < BK; kk++) {
            float a[4], b[4];
            #pragma unroll
            for (int i = 0; i < 4; i++) a[i] = As[kk][ty*4 + i];
            #pragma unroll
            for (int j = 0; j < 4; j++) b[j] = Bs[kk][tx*4 + j];
            #pragma unroll
            for (int i = 0; i < 4; i++)
                #pragma unroll
                for (int j = 0; j < 4; j++)
                    acc[i][j] = fmaf(a[i], b[j], acc[i][j]);
        }
        __syncthreads();
    }
    #pragma unroll
    for (int i = 0; i < 4; i++) {
        int m = ty*4 + i;
        if (m < rows) {
            size_t row = (size_t)(base + m) * Hh + n0;
            #pragma unroll
            for (int j = 0; j < 4; j++) {
                float c = acc[i][j];
                // exact gelu
                g_h[row + tx*4 + j] = 0.5f * c * (1.f + erff(c * 0.7071067811865475f));
            }
        }
    }
}

// y[slot, :] = h[slot, :] @ W2[e]
__global__ void gemm2_kernel(const float* __restrict__ W2) {
    int e = blockIdx.z;
    int cnt = g_counts[e];
    int m0 = blockIdx.y * BM;
    if (m0 >= cnt) return;
    int n0 = blockIdx.x * BN;
    int base = g_offsets[e] + m0;
    int rows = min(BM, cnt - m0);
    const float* Bw = W2 + (size_t)e * Hh * Dd;

    __shared__ float As[BK][BM];
    __shared__ float Bs[BK][BN];
    int t = threadIdx.x;
    float acc[4][4] = {};
    int tx = t & 15, ty = t >> 4;

    for (int k0 = 0; k0 < Hh; k0 += BK) {
        #pragma unroll
        for (int i = 0; i < 4; i++) {
            int idx = t + i * 256;
            int m = idx >> 4, kk = idx & 15;
            As[kk][m] = (m < rows) ? g_h[(size_t)(base + m) * Hh + k0 + kk] : 0.f;
        }
        #pragma unroll
        for (int i = 0; i < 4; i++) {
            int idx = t + i * 256;
            int kk = idx >> 6, nn = idx & 63;
            Bs[kk][nn] = Bw[(size_t)(k0 + kk) * Dd + n0 + nn];
        }
        __syncthreads();
        #pragma unroll
        for (int kk = 0; kk < BK; kk++) {
            float a[4], b[4];
            #pragma unroll
            for (int i = 0; i < 4; i++) a[i] = As[kk][ty*4 + i];
            #pragma unroll
            for (int j = 0; j < 4; j++) b[j] = Bs[kk][tx*4 + j];
            #pragma unroll
            for (int i = 0; i < 4; i++)
                #pragma unroll
                for (int j = 0; j < 4; j++)
                    acc[i][j] = fmaf(a[i], b[j], acc[i][j]);
        }
        __syncthreads();
    }
    #pragma unroll
    for (int i = 0; i < 4; i++) {
        int m = ty*4 + i;
        if (m < rows) {
            size_t row = (size_t)(base + m) * Dd + n0;
            #pragma unroll
            for (int j = 0; j < 4; j++)
                g_y[row + tx*4 + j] = acc[i][j];
        }
    }
}

// out[n, :] = w0 * y[slot0(n), :] + w1 * y[slot1(n), :]
__global__ void combine_kernel(float* __restrict__ out) {
    int idx = blockIdx.x * 256 + threadIdx.x;
    if (idx >= Nn * Dd) return;
    int n = idx / Dd, d = idx - n * Dd;
    int s0 = g_tok_slot[n*2], s1 = g_tok_slot[n*2 + 1];
    float w0 = g_topw[n*2], w1 = g_topw[n*2 + 1];
    out[idx] = w0 * g_y[(size_t)s0 * Dd + d] + w1 * g_y[(size_t)s1 * Dd + d];
}

// aux_loss = 0.01 * mean((probs.mean(0) - 1/E)^2); broadcast into any tail
__global__ void aux_kernel(float* __restrict__ out, int out_size) {
    int extra = out_size - Nn * Dd;
    if (extra <= 0) return;
    int i = blockIdx.x * 256 + threadIdx.x;
    if (i >= extra) return;
    float aux = 0.f;
    #pragma unroll
    for (int e = 0; e < Ee; e++) {
        float tpe = g_probsum[e] * (1.0f / (float)Nn);
        float dlt = tpe - 1.0f / (float)Ee;
        aux += dlt * dlt;
    }
    aux = 0.01f * aux / (float)Ee;
    out[Nn * Dd + i] = aux;
}

// ---------------- launch ----------------------------------------------------
extern "C" void kernel_launch(void* const* d_in, const int* in_sizes, int n_in,
                              void* d_out, int out_size) {
    const float* x  = (const float*)d_in[0];
    const float* Wr = (const float*)d_in[1];
    const float* W1 = (const float*)d_in[2];
    const float* W2 = (const float*)d_in[3];
    float* out = (float*)d_out;

    init_kernel<<<1, 32>>>();
    routing_kernel<<<Nn, 128>>>(x, Wr);
    offsets_kernel<<<1, 32>>>();
    fill_kernel<<<(NK + 255) / 256, 256>>>();
    gemm1_kernel<<<dim3(Hh / BN, Nn / BM, Ee), 256>>>(x, W1);
    gemm2_kernel<<<dim3(Dd / BN, Nn / BM, Ee), 256>>>(W2);
    combine_kernel<<<(Nn * Dd + 255) / 256, 256>>>(out);
    aux_kernel<<<16, 256>>>(out, out_size);
}

// round 2
// speedup vs baseline: 4.1382x; 4.1382x over previous
#include <cuda_runtime.h>
#include <math.h>
#include <stdint.h>

#define Bb 2
#define Tt 1024
#define Dd 768
#define Hh 3072
#define Ee 8
#define Kk 2
#define Nn (Bb*Tt)      // 2048 tokens
#define NK (Nn*Kk)      // 4096 (token, expert) slots

// ---------------- scratch (device globals; no allocation allowed) ----------
__device__ float g_h[(size_t)NK * Hh];     // gelu(x @ W1[e]) per slot
__device__ float g_y[(size_t)NK * Dd];     // h @ W2[e] per slot
__device__ int   g_counts[Ee];
__device__ int   g_offsets[Ee + 1];
__device__ int   g_topi[NK];
__device__ float g_topw[NK];
__device__ int   g_pos[NK];
__device__ int   g_slot_tok[NK];           // slot -> token
__device__ int   g_tok_slot[NK];           // (token,k) -> slot
__device__ float g_probsum[Ee];

// ---------------- helpers ---------------------------------------------------
__device__ __forceinline__ uint32_t sptr(const void* p) {
    return (uint32_t)__cvta_generic_to_shared(p);
}
__device__ __forceinline__ uint32_t f2tf(float x) {
    uint32_t u;
    asm("cvt.rna.tf32.f32 %0, %1;" : "=r"(u) : "f"(x));
    return u;
}
__device__ __forceinline__ void cp16(uint32_t dst, const void* src, int pbytes) {
    asm volatile("cp.async.cg.shared.global [%0], [%1], 16, %2;"
                 :: "r"(dst), "l"(src), "r"(pbytes));
}
__device__ __forceinline__ void cp_commit() {
    asm volatile("cp.async.commit_group;" ::: "memory");
}
__device__ __forceinline__ void mma_tf32(float c[4], uint32_t a0, uint32_t a1,
                                         uint32_t a2, uint32_t a3,
                                         uint32_t b0, uint32_t b1) {
    asm volatile(
        "mma.sync.aligned.m16n8k8.row.col.f32.tf32.tf32.f32 "
        "{%0,%1,%2,%3}, {%4,%5,%6,%7}, {%8,%9}, {%0,%1,%2,%3};"
        : "+f"(c[0]), "+f"(c[1]), "+f"(c[2]), "+f"(c[3])
        : "r"(a0), "r"(a1), "r"(a2), "r"(a3), "r"(b0), "r"(b1));
}
__device__ __forceinline__ float gelu_exact(float c) {
    return 0.5f * c * (1.f + erff(c * 0.7071067811865475f));
}

// ---------------- tiny setup kernels ---------------------------------------
__global__ void init_kernel() {
    int t = threadIdx.x;
    if (t < Ee) { g_counts[t] = 0; g_probsum[t] = 0.f; }
}

__global__ void routing_kernel(const float* __restrict__ x,
                               const float* __restrict__ Wr) {
    int n = blockIdx.x;
    int t = threadIdx.x;
    const float* xr = x + (size_t)n * Dd;
    float a0 = 0.f, a1 = 0.f, a2 = 0.f;
    for (int d = t; d < Dd; d += 128) {
        float xv = xr[d];
        a0 += xv * Wr[d];
        a1 += xv * Wr[Dd + d];
        a2 += xv * Wr[2 * Dd + d];
    }
    __shared__ float s0[128], s1[128], s2[128];
    s0[t] = a0; s1[t] = a1; s2[t] = a2;
    __syncthreads();
    for (int off = 64; off > 0; off >>= 1) {
        if (t < off) { s0[t] += s0[t+off]; s1[t] += s1[t+off]; s2[t] += s2[t+off]; }
        __syncthreads();
    }
    if (t == 0) {
        float z0 = s0[0], z1 = s1[0], z2 = s2[0];
        const float inv3 = 0.57735026918962576f;
        float logits[Ee];
        #pragma unroll
        for (int e = 0; e < Ee; e++) {
            float d0 = (e & 4) ? 1.f : -1.f;
            float d1 = (e & 2) ? 1.f : -1.f;
            float d2 = (e & 1) ? 1.f : -1.f;
            logits[e] = (d0 * z0 + d1 * z1 + d2 * z2) * inv3;
        }
        float m = logits[0];
        #pragma unroll
        for (int e = 1; e < Ee; e++) m = fmaxf(m, logits[e]);
        float p[Ee]; float sum = 0.f;
        #pragma unroll
        for (int e = 0; e < Ee; e++) { p[e] = expf(logits[e] - m); sum += p[e]; }
        float invs = 1.f / sum;
        #pragma unroll
        for (int e = 0; e < Ee; e++) atomicAdd(&g_probsum[e], p[e] * invs);
        int i0 = 0;
        #pragma unroll
        for (int e = 1; e < Ee; e++) if (p[e] > p[i0]) i0 = e;
        int i1 = (i0 == 0) ? 1 : 0;
        #pragma unroll
        for (int e = 0; e < Ee; e++) if (e != i0 && p[e] > p[i1]) i1 = e;
        float v0 = p[i0], v1 = p[i1];
        float wd = 1.f / (v0 + v1);
        g_topi[n*2]   = i0; g_topi[n*2+1] = i1;
        g_topw[n*2]   = v0 * wd; g_topw[n*2+1] = v1 * wd;
        g_pos[n*2]    = atomicAdd(&g_counts[i0], 1);
        g_pos[n*2+1]  = atomicAdd(&g_counts[i1], 1);
    }
}

__global__ void offsets_kernel() {
    if (threadIdx.x == 0 && blockIdx.x == 0) {
        int s = 0;
        for (int e = 0; e < Ee; e++) { g_offsets[e] = s; s += g_counts[e]; }
        g_offsets[Ee] = s;
    }
}

__global__ void fill_kernel() {
    int idx = blockIdx.x * 256 + threadIdx.x;
    if (idx >= NK) return;
    int e = g_topi[idx];
    int slot = g_offsets[e] + g_pos[idx];
    g_slot_tok[slot] = idx >> 1;
    g_tok_slot[idx]  = slot;
}

// ---------------- tf32 tensor-core GEMMs ------------------------------------
// Block tile 128x128, BK=16. 256 threads = 8 warps in 2(m) x 4(n) grid,
// warp tile 64x32 => 4x4 fragments of m16n8k8. cp.async double buffer.
#define BMT 128
#define BNT 128
#define BKT 16
#define AST 20    // As row stride (floats): 128 rows x [BKT + 4]
#define BST 136   // Bs row stride (floats): BKT rows x [BNT + 8]

// h[slot,:] = gelu( x[token(slot),:] @ W1[e] )   (A gathered, K=768)
__global__ __launch_bounds__(256) void gemm1_kernel(const float* __restrict__ x,
                                                    const float* __restrict__ W1) {
    int e = blockIdx.z;
    int cnt = g_counts[e];
    int m0 = blockIdx.y * BMT;
    if (m0 >= cnt) return;
    int n0 = blockIdx.x * BNT;
    int base = g_offsets[e] + m0;
    int rows = min(BMT, cnt - m0);
    const float* Bw = W1 + (size_t)e * Dd * Hh;

    __shared__ float As[2][BMT][AST];
    __shared__ float Bs[2][BKT][BST];
    __shared__ int   stok[BMT];

    int t = threadIdx.x;
    int wid = t >> 5, lane = t & 31;
    int gid = lane >> 2, tig = lane & 3;
    int wm0 = (wid & 1) * 64;
    int wn0 = (wid >> 1) * 32;

    if (t < BMT) stok[t] = (t < rows) ? g_slot_tok[base + t] : -1;
    __syncthreads();

    // per-thread load coords: 512 float4 per tile for A and for B
    int am = (t + 0) >> 2;            // A: i = t + j*256; m = i>>2, kq = i&3
    int akq = t & 3;

    const int NT = Dd / BKT;          // 48
    float acc[4][4][4] = {};

    auto issue = [&](int kt, int buf) {
        #pragma unroll
        for (int j = 0; j < 2; j++) {
            int m = am + j * 64;
            int tok = stok[m];
            uint32_t dst = sptr(&As[buf][m][akq * 4]);
            const float* src = x + (size_t)max(tok, 0) * Dd + kt * BKT + akq * 4;
            cp16(dst, src, (tok >= 0) ? 16 : 0);
        }
        #pragma unroll
        for (int j = 0; j < 2; j++) {
            int i = t + j * 256;
            int kk = i >> 5, n4 = i & 31;
            uint32_t dst = sptr(&Bs[buf][kk][n4 * 4]);
            const float* src = Bw + (size_t)(kt * BKT + kk) * Hh + n0 + n4 * 4;
            cp16(dst, src, 16);
        }
        cp_commit();
    };

    issue(0, 0);
    for (int kt = 0; kt < NT; kt++) {
        int cur = kt & 1;
        if (kt + 1 < NT) {
            issue(kt + 1, (kt + 1) & 1);
            asm volatile("cp.async.wait_group 1;" ::: "memory");
        } else {
            asm volatile("cp.async.wait_group 0;" ::: "memory");
        }
        __syncthreads();
        #pragma unroll
        for (int ks = 0; ks < 2; ks++) {
            int kb = ks * 8;
            uint32_t a[4][4], b[4][2];
            #pragma unroll
            for (int mi = 0; mi < 4; mi++) {
                int r = wm0 + mi * 16 + gid;
                a[mi][0] = f2tf(As[cur][r][kb + tig]);
                a[mi][1] = f2tf(As[cur][r + 8][kb + tig]);
                a[mi][2] = f2tf(As[cur][r][kb + tig + 4]);
                a[mi][3] = f2tf(As[cur][r + 8][kb + tig + 4]);
            }
            #pragma unroll
            for (int ni = 0; ni < 4; ni++) {
                int c = wn0 + ni * 8 + gid;
                b[ni][0] = f2tf(Bs[cur][kb + tig][c]);
                b[ni][1] = f2tf(Bs[cur][kb + tig + 4][c]);
            }
            #pragma unroll
            for (int mi = 0; mi < 4; mi++)
                #pragma unroll
                for (int ni = 0; ni < 4; ni++)
                    mma_tf32(acc[mi][ni], a[mi][0], a[mi][1], a[mi][2], a[mi][3],
                             b[ni][0], b[ni][1]);
        }
        __syncthreads();
    }

    // epilogue: gelu + store
    #pragma unroll
    for (int mi = 0; mi < 4; mi++) {
        int r0 = wm0 + mi * 16 + gid;
        #pragma unroll
        for (int ni = 0; ni < 4; ni++) {
            int c = n0 + wn0 + ni * 8 + tig * 2;
            if (r0 < rows) {
                size_t o = (size_t)(base + r0) * Hh + c;
                g_h[o]     = gelu_exact(acc[mi][ni][0]);
                g_h[o + 1] = gelu_exact(acc[mi][ni][1]);
            }
            if (r0 + 8 < rows) {
                size_t o = (size_t)(base + r0 + 8) * Hh + c;
                g_h[o]     = gelu_exact(acc[mi][ni][2]);
                g_h[o + 1] = gelu_exact(acc[mi][ni][3]);
            }
        }
    }
}

// y[slot,:] = h[slot,:] @ W2[e]   (K=3072, N=768)
__global__ __launch_bounds__(256) void gemm2_kernel(const float* __restrict__ W2) {
    int e = blockIdx.z;
    int cnt = g_counts[e];
    int m0 = blockIdx.y * BMT;
    if (m0 >= cnt) return;
    int n0 = blockIdx.x * BNT;
    int base = g_offsets[e] + m0;
    int rows = min(BMT, cnt - m0);
    const float* Bw = W2 + (size_t)e * Hh * Dd;

    __shared__ float As[2][BMT][AST];
    __shared__ float Bs[2][BKT][BST];

    int t = threadIdx.x;
    int wid = t >> 5, lane = t & 31;
    int gid = lane >> 2, tig = lane & 3;
    int wm0 = (wid & 1) * 64;
    int wn0 = (wid >> 1) * 32;

    int am = t >> 2;
    int akq = t & 3;

    const int NT = Hh / BKT;          // 192
    float acc[4][4][4] = {};

    auto issue = [&](int kt, int buf) {
        #pragma unroll
        for (int j = 0; j < 2; j++) {
            int m = am + j * 64;
            uint32_t dst = sptr(&As[buf][m][akq * 4]);
            const float* src = g_h + (size_t)(base + min(m, rows - 1)) * Hh + kt * BKT + akq * 4;
            cp16(dst, src, (m < rows) ? 16 : 0);
        }
        #pragma unroll
        for (int j = 0; j < 2; j++) {
            int i = t + j * 256;
            int kk = i >> 5, n4 = i & 31;
            uint32_t dst = sptr(&Bs[buf][kk][n4 * 4]);
            const float* src = Bw + (size_t)(kt * BKT + kk) * Dd + n0 + n4 * 4;
            cp16(dst, src, 16);
        }
        cp_commit();
    };

    issue(0, 0);
    for (int kt = 0; kt < NT; kt++) {
        int cur = kt & 1;
        if (kt + 1 < NT) {
            issue(kt + 1, (kt + 1) & 1);
            asm volatile("cp.async.wait_group 1;" ::: "memory");
        } else {
            asm volatile("cp.async.wait_group 0;" ::: "memory");
        }
        __syncthreads();
        #pragma unroll
        for (int ks = 0; ks < 2; ks++) {
            int kb = ks * 8;
            uint32_t a[4][4], b[4][2];
            #pragma unroll
            for (int mi = 0; mi < 4; mi++) {
                int r = wm0 + mi * 16 + gid;
                a[mi][0] = f2tf(As[cur][r][kb + tig]);
                a[mi][1] = f2tf(As[cur][r + 8][kb + tig]);
                a[mi][2] = f2tf(As[cur][r][kb + tig + 4]);
                a[mi][3] = f2tf(As[cur][r + 8][kb + tig + 4]);
            }
            #pragma unroll
            for (int ni = 0; ni < 4; ni++) {
                int c = wn0 + ni * 8 + gid;
                b[ni][0] = f2tf(Bs[cur][kb + tig][c]);
                b[ni][1] = f2tf(Bs[cur][kb + tig + 4][c]);
            }
            #pragma unroll
            for (int mi = 0; mi < 4; mi++)
                #pragma unroll
                for (int ni = 0; ni < 4; ni++)
                    mma_tf32(acc[mi][ni], a[mi][0], a[mi][1], a[mi][2], a[mi][3],
                             b[ni][0], b[ni][1]);
        }
        __syncthreads();
    }

    #pragma unroll
    for (int mi = 0; mi < 4; mi++) {
        int r0 = wm0 + mi * 16 + gid;
        #pragma unroll
        for (int ni = 0; ni < 4; ni++) {
            int c = n0 + wn0 + ni * 8 + tig * 2;
            if (r0 < rows) {
                size_t o = (size_t)(base + r0) * Dd + c;
                g_y[o]     = acc[mi][ni][0];
                g_y[o + 1] = acc[mi][ni][1];
            }
            if (r0 + 8 < rows) {
                size_t o = (size_t)(base + r0 + 8) * Dd + c;
                g_y[o]     = acc[mi][ni][2];
                g_y[o + 1] = acc[mi][ni][3];
            }
        }
    }
}

// out[n,:] = w0 * y[slot0(n),:] + w1 * y[slot1(n),:]
__global__ void combine_kernel(float* __restrict__ out) {
    int idx = blockIdx.x * 256 + threadIdx.x;
    if (idx >= Nn * Dd) return;
    int n = idx / Dd, d = idx - n * Dd;
    int s0 = g_tok_slot[n*2], s1 = g_tok_slot[n*2 + 1];
    float w0 = g_topw[n*2], w1 = g_topw[n*2 + 1];
    out[idx] = w0 * g_y[(size_t)s0 * Dd + d] + w1 * g_y[(size_t)s1 * Dd + d];
}

__global__ void aux_kernel(float* __restrict__ out, int out_size) {
    int extra = out_size - Nn * Dd;
    if (extra <= 0) return;
    int i = blockIdx.x * 256 + threadIdx.x;
    if (i >= extra) return;
    float aux = 0.f;
    #pragma unroll
    for (int e = 0; e < Ee; e++) {
        float tpe = g_probsum[e] * (1.0f / (float)Nn);
        float dlt = tpe - 1.0f / (float)Ee;
        aux += dlt * dlt;
    }
    aux = 0.01f * aux / (float)Ee;
    out[Nn * Dd + i] = aux;
}

// ---------------- launch ----------------------------------------------------
extern "C" void kernel_launch(void* const* d_in, const int* in_sizes, int n_in,
                              void* d_out, int out_size) {
    const float* x  = (const float*)d_in[0];
    const float* Wr = (const float*)d_in[1];
    const float* W1 = (const float*)d_in[2];
    const float* W2 = (const float*)d_in[3];
    float* out = (float*)d_out;

    init_kernel<<<1, 32>>>();
    routing_kernel<<<Nn, 128>>>(x, Wr);
    offsets_kernel<<<1, 32>>>();
    fill_kernel<<<(NK + 255) / 256, 256>>>();
    gemm1_kernel<<<dim3(Hh / BNT, Nn / BMT, Ee), 256>>>(x, W1);
    gemm2_kernel<<<dim3(Dd / BNT, Nn / BMT, Ee), 256>>>(W2);
    combine_kernel<<<(Nn * Dd + 255) / 256, 256>>>(out);
    aux_kernel<<<16, 256>>>(out, out_size);
}

// round 6
// speedup vs baseline: 4.8825x; 1.1799x over previous
#include <cuda_runtime.h>
#include <math.h>
#include <stdint.h>

#define Bb 2
#define Tt 1024
#define Dd 768
#define Hh 3072
#define Ee 8
#define Nn (Bb*Tt)      // 2048 tokens
#define NK (Nn*2)       // 4096 slots

// ---------------- scratch (device globals) ----------------------------------
__device__ float g_h[(size_t)NK * Hh];     // gelu(x@W1) per slot (tf32-rounded)
__device__ float g_y[(size_t)NK * Dd];     // h@W2 per slot
__device__ float g_xtf[(size_t)Nn * Dd];   // tf32-rounded x
__device__ int   g_counts[Ee];
__device__ int   g_offsets[Ee + 1];
__device__ int   g_topi[NK];
__device__ float g_topw[NK];
__device__ int   g_pos[NK];
__device__ int   g_slot_tok[NK];
__device__ int   g_tok_slot[NK];
__device__ float g_probsum[Ee];

// ---------------- helpers ----------------------------------------------------
__device__ __forceinline__ uint32_t f2tf(float x) {
    uint32_t u;
    asm("cvt.rna.tf32.f32 %0, %1;" : "=r"(u) : "f"(x));
    return u;
}
__device__ __forceinline__ void cp16(uint32_t dst, const void* src, int pbytes) {
    asm volatile("cp.async.cg.shared.global [%0], [%1], 16, %2;"
                 :: "r"(dst), "l"(src), "r"(pbytes));
}
__device__ __forceinline__ void mma_tf32(float c[4], uint32_t a0, uint32_t a1,
                                         uint32_t a2, uint32_t a3,
                                         uint32_t b0, uint32_t b1) {
    asm volatile(
        "mma.sync.aligned.m16n8k8.row.col.f32.tf32.tf32.f32 "
        "{%0,%1,%2,%3}, {%4,%5,%6,%7}, {%8,%9}, {%0,%1,%2,%3};"
        : "+f"(c[0]), "+f"(c[1]), "+f"(c[2]), "+f"(c[3])
        : "r"(a0), "r"(a1), "r"(a2), "r"(a3), "r"(b0), "r"(b1));
}
__device__ __forceinline__ void ldsm4(uint32_t a[4], uint32_t addr) {
    asm volatile("ldmatrix.sync.aligned.m8n8.x4.shared.b16 {%0,%1,%2,%3}, [%4];"
                 : "=r"(a[0]), "=r"(a[1]), "=r"(a[2]), "=r"(a[3]) : "r"(addr));
}
__device__ __forceinline__ float gelu_exact(float c) {
    return 0.5f * c * (1.f + erff(c * 0.7071067811865475f));
}

// ---------------- routing ----------------------------------------------------
__global__ void init_kernel() {
    int t = threadIdx.x;
    if (t < Ee) { g_counts[t] = 0; g_probsum[t] = 0.f; }
}

__global__ void routing_kernel(const float* __restrict__ x,
                               const float* __restrict__ Wr) {
    int n = blockIdx.x;
    int t = threadIdx.x;
    const float* xr = x + (size_t)n * Dd;
    float a0 = 0.f, a1 = 0.f, a2 = 0.f;
    for (int d = t; d < Dd; d += 128) {
        float xv = xr[d];
        a0 += xv * Wr[d];
        a1 += xv * Wr[Dd + d];
        a2 += xv * Wr[2 * Dd + d];
    }
    __shared__ float s0[128], s1[128], s2[128];
    s0[t] = a0; s1[t] = a1; s2[t] = a2;
    __syncthreads();
    for (int off = 64; off > 0; off >>= 1) {
        if (t < off) { s0[t] += s0[t+off]; s1[t] += s1[t+off]; s2[t] += s2[t+off]; }
        __syncthreads();
    }
    if (t == 0) {
        float z0 = s0[0], z1 = s1[0], z2 = s2[0];
        const float inv3 = 0.57735026918962576f;
        float logits[Ee];
        #pragma unroll
        for (int e = 0; e < Ee; e++) {
            float d0 = (e & 4) ? 1.f : -1.f;
            float d1 = (e & 2) ? 1.f : -1.f;
            float d2 = (e & 1) ? 1.f : -1.f;
            logits[e] = (d0 * z0 + d1 * z1 + d2 * z2) * inv3;
        }
        float m = logits[0];
        #pragma unroll
        for (int e = 1; e < Ee; e++) m = fmaxf(m, logits[e]);
        float p[Ee]; float sum = 0.f;
        #pragma unroll
        for (int e = 0; e < Ee; e++) { p[e] = expf(logits[e] - m); sum += p[e]; }
        float invs = 1.f / sum;
        #pragma unroll
        for (int e = 0; e < Ee; e++) atomicAdd(&g_probsum[e], p[e] * invs);
        int i0 = 0;
        #pragma unroll
        for (int e = 1; e < Ee; e++) if (p[e] > p[i0]) i0 = e;
        int i1 = (i0 == 0) ? 1 : 0;
        #pragma unroll
        for (int e = 0; e < Ee; e++) if (e != i0 && p[e] > p[i1]) i1 = e;
        float v0 = p[i0], v1 = p[i1];
        float wd = 1.f / (v0 + v1);
        g_topi[n*2]   = i0; g_topi[n*2+1] = i1;
        g_topw[n*2]   = v0 * wd; g_topw[n*2+1] = v1 * wd;
        g_pos[n*2]    = atomicAdd(&g_counts[i0], 1);
        g_pos[n*2+1]  = atomicAdd(&g_counts[i1], 1);
    }
}

__global__ void offsets_kernel() {
    if (threadIdx.x == 0 && blockIdx.x == 0) {
        int s = 0;
        for (int e = 0; e < Ee; e++) { g_offsets[e] = s; s += g_counts[e]; }
        g_offsets[Ee] = s;
    }
}

__global__ void fill_kernel() {
    int idx = blockIdx.x * 256 + threadIdx.x;
    if (idx >= NK) return;
    int e = g_topi[idx];
    int slot = g_offsets[e] + g_pos[idx];
    g_slot_tok[slot] = idx >> 1;
    g_tok_slot[idx]  = slot;
}

// pre-round x to tf32 once (keeps cvt out of the GEMM hot loop)
__global__ void xtf_kernel(const float* __restrict__ x) {
    int i = blockIdx.x * 256 + threadIdx.x;
    if (i < Nn * Dd) g_xtf[i] = __uint_as_float(f2tf(x[i]));
}

// ---------------- tf32 tensor-core GEMMs (ldmatrix + 3-stage cp.async) ------
// Block tile 128x128, BK=32. 8 warps 2(m)x4(n), warp tile 64x32, 4x4 m16n8k8.
// Smem: A[m][k] rows 128B, B[k][n] rows 512B, 16B-unit XOR swizzle (unit ^ (row&7)).
#define BKT 32
#define A_FL 4096                 // 128*32 floats per stage
#define B_FL 4096                 // 32*128 floats per stage
#define GEMM_SMEM (3*(A_FL+B_FL)*4 + 512)

template<bool G1>
__global__ __launch_bounds__(256, 2) void moe_gemm(const float* __restrict__ Wglob) {
    constexpr int KTOT = G1 ? Dd : Hh;
    constexpr int NSTR = G1 ? Hh : Dd;
    constexpr int NT = KTOT / BKT;       // 24 / 96

    int e = blockIdx.z;
    int cnt = g_counts[e];
    int m0 = blockIdx.y * 128;
    if (m0 >= cnt) return;
    int n0 = blockIdx.x * 128;
    int base = g_offsets[e] + m0;
    int rows = min(128, cnt - m0);

    extern __shared__ float sm[];
    float* As = sm;                       // 3 stages x 4096 floats
    float* Bs = sm + 3 * A_FL;
    int* stok = (int*)(sm + 3 * (A_FL + B_FL));
    uint32_t uA = (uint32_t)__cvta_generic_to_shared(As);
    uint32_t uB = (uint32_t)__cvta_generic_to_shared(Bs);

    int t = threadIdx.x, wid = t >> 5, lane = t & 31;
    int wm0 = (wid & 1) * 64, wn0 = (wid >> 1) * 32;
    int gid = lane >> 2, tig = lane & 3;
    // ldmatrix x4 lane->tile mapping: lanes 0-7 tile0 (rows+0,k+0), 8-15 tile1
    // (rows+8,k+0), 16-23 tile2 (rows+0,k+4), 24-31 tile3 (rows+8,k+4)
    int rowa0 = wm0 + (lane & 7) + ((lane >> 3) & 1) * 8;
    int kpart = (lane >> 4) & 1;

    const float* Wb = Wglob + (size_t)e * Dd * Hh;

    if (G1 && t < 128) stok[t] = (t < rows) ? g_slot_tok[base + t] : -1;
    __syncthreads();

    auto issue = [&](int kt) {
        int buf = kt % 3;
        uint32_t ab = uA + buf * (A_FL * 4);
        uint32_t bb = uB + buf * (B_FL * 4);
        #pragma unroll
        for (int i = 0; i < 4; i++) {                 // A: 1024 x 16B
            int idx = i * 256 + t;
            int r = idx >> 3, u = idx & 7;
            uint32_t dst = ab + r * 128 + ((u ^ (r & 7)) << 4);
            if (G1) {
                int tok = stok[r];
                cp16(dst, g_xtf + (size_t)max(tok, 0) * KTOT + kt * BKT + u * 4,
                     (tok >= 0) ? 16 : 0);
            } else {
                cp16(dst, g_h + (size_t)(base + min(r, rows - 1)) * KTOT + kt * BKT + u * 4,
                     (r < rows) ? 16 : 0);
            }
        }
        #pragma unroll
        for (int i = 0; i < 4; i++) {                 // B: 1024 x 16B
            int idx = i * 256 + t;
            int k = idx >> 5, u = idx & 31;
            uint32_t dst = bb + k * 512 + ((u ^ (k & 7)) << 4);
            cp16(dst, Wb + (size_t)(kt * BKT + k) * NSTR + n0 + u * 4, 16);
        }
        asm volatile("cp.async.commit_group;" ::: "memory");
    };

    issue(0);
    issue(1);

    float acc[4][4][4] = {};

    for (int j = 0; j < NT; j++) {
        int buf = j % 3;
        if (j <= NT - 2) asm volatile("cp.async.wait_group 1;" ::: "memory");
        else             asm volatile("cp.async.wait_group 0;" ::: "memory");
        __syncthreads();
        if (j + 2 < NT) issue(j + 2);

        uint32_t ab = uA + buf * (A_FL * 4);
        float* Bsf = Bs + buf * B_FL;

        #pragma unroll
        for (int ks = 0; ks < 4; ks++) {
            uint32_t a[4][4];
            #pragma unroll
            for (int mi = 0; mi < 4; mi++) {
                int r = rowa0 + mi * 16;
                uint32_t addr = ab + r * 128 + (((2 * ks + kpart) ^ (r & 7)) << 4);
                ldsm4(a[mi], addr);
            }
            uint32_t b[4][2];
            #pragma unroll
            for (int ni = 0; ni < 4; ni++) {
                int n = wn0 + ni * 8 + gid;
                int u = n >> 2, n3 = n & 3;
                // store swizzle was u ^ (k&7); (ks*8+tig)&7 == tig, +4 likewise
                float f0 = Bsf[(ks * 8 + tig) * 128 + ((u ^ tig) << 2) + n3];
                float f1 = Bsf[(ks * 8 + tig + 4) * 128 + ((u ^ (tig + 4)) << 2) + n3];
                b[ni][0] = f2tf(f0);
                b[ni][1] = f2tf(f1);
            }
            #pragma unroll
            for (int mi = 0; mi < 4; mi++)
                #pragma unroll
                for (int ni = 0; ni < 4; ni++)
                    mma_tf32(acc[mi][ni], a[mi][0], a[mi][1], a[mi][2], a[mi][3],
                             b[ni][0], b[ni][1]);
        }
    }

    // epilogue
    float* Cout = G1 ? g_h : g_y;
    #pragma unroll
    for (int mi = 0; mi < 4; mi++) {
        int r0 = wm0 + mi * 16 + gid;
        #pragma unroll
        for (int ni = 0; ni < 4; ni++) {
            int c = n0 + wn0 + ni * 8 + tig * 2;
            if (r0 < rows) {
                size_t o = (size_t)(base + r0) * NSTR + c;
                if (G1) {
                    Cout[o]     = __uint_as_float(f2tf(gelu_exact(acc[mi][ni][0])));
                    Cout[o + 1] = __uint_as_float(f2tf(gelu_exact(acc[mi][ni][1])));
                } else {
                    Cout[o]     = acc[mi][ni][0];
                    Cout[o + 1] = acc[mi][ni][1];
                }
            }
            if (r0 + 8 < rows) {
                size_t o = (size_t)(base + r0 + 8) * NSTR + c;
                if (G1) {
                    Cout[o]     = __uint_as_float(f2tf(gelu_exact(acc[mi][ni][2])));
                    Cout[o + 1] = __uint_as_float(f2tf(gelu_exact(acc[mi][ni][3])));
                } else {
                    Cout[o]     = acc[mi][ni][2];
                    Cout[o + 1] = acc[mi][ni][3];
                }
            }
        }
    }
}

// ---------------- combine + aux ---------------------------------------------
__global__ void combine_kernel(float* __restrict__ out) {
    int idx = blockIdx.x * 256 + threadIdx.x;
    if (idx >= Nn * (Dd / 4)) return;
    int n = idx / (Dd / 4), q = idx - n * (Dd / 4);
    int s0 = g_tok_slot[n*2], s1 = g_tok_slot[n*2 + 1];
    float w0 = g_topw[n*2], w1 = g_topw[n*2 + 1];
    float4 y0 = *(const float4*)(g_y + (size_t)s0 * Dd + q * 4);
    float4 y1 = *(const float4*)(g_y + (size_t)s1 * Dd + q * 4);
    float4 o;
    o.x = w0 * y0.x + w1 * y1.x;
    o.y = w0 * y0.y + w1 * y1.y;
    o.z = w0 * y0.z + w1 * y1.z;
    o.w = w0 * y0.w + w1 * y1.w;
    *(float4*)(out + (size_t)n * Dd + q * 4) = o;
}

__global__ void aux_kernel(float* __restrict__ out, int out_size) {
    int extra = out_size - Nn * Dd;
    if (extra <= 0) return;
    int i = blockIdx.x * 256 + threadIdx.x;
    if (i >= extra) return;
    float aux = 0.f;
    #pragma unroll
    for (int e = 0; e < Ee; e++) {
        float tpe = g_probsum[e] * (1.0f / (float)Nn);
        float dlt = tpe - 1.0f / (float)Ee;
        aux += dlt * dlt;
    }
    aux = 0.01f * aux / (float)Ee;
    out[Nn * Dd + i] = aux;
}

// ---------------- launch -----------------------------------------------------
extern "C" void kernel_launch(void* const* d_in, const int* in_sizes, int n_in,
                              void* d_out, int out_size) {
    const float* x  = (const float*)d_in[0];
    const float* Wr = (const float*)d_in[1];
    const float* W1 = (const float*)d_in[2];
    const float* W2 = (const float*)d_in[3];
    float* out = (float*)d_out;

    cudaFuncSetAttribute(moe_gemm<true>,  cudaFuncAttributeMaxDynamicSharedMemorySize, GEMM_SMEM);
    cudaFuncSetAttribute(moe_gemm<false>, cudaFuncAttributeMaxDynamicSharedMemorySize, GEMM_SMEM);

    init_kernel<<<1, 32>>>();
    routing_kernel<<<Nn, 128>>>(x, Wr);
    xtf_kernel<<<(Nn * Dd + 255) / 256, 256>>>(x);
    offsets_kernel<<<1, 32>>>();
    fill_kernel<<<(NK + 255) / 256, 256>>>();
    moe_gemm<true><<<dim3(Hh / 128, Nn / 128, Ee), 256, GEMM_SMEM>>>(W1);
    moe_gemm<false><<<dim3(Dd / 128, Nn / 128, Ee), 256, GEMM_SMEM>>>(W2);
    combine_kernel<<<(Nn * (Dd / 4) + 255) / 256, 256>>>(out);
    aux_kernel<<<16, 256>>>(out, out_size);
}

// round 8
// speedup vs baseline: 7.2670x; 1.4884x over previous
#include <cuda_runtime.h>
#include <cuda_fp16.h>
#include <math.h>
#include <stdint.h>

#define Bb 2
#define Tt 1024
#define Dd 768
#define Hh 3072
#define Ee 8
#define Nn (Bb*Tt)      // 2048 tokens
#define NK (Nn*2)       // 4096 slots

// ---------------- scratch (device globals) ----------------------------------
__device__ __half g_hh[(size_t)NK * Hh];    // gelu(x@W1) per slot, fp16
__device__ float  g_y[(size_t)NK * Dd];     // h@W2 per slot
__device__ __half g_xh[(size_t)Nn * Dd];    // fp16 x
__device__ __half g_w1h[(size_t)Ee * Dd * Hh];
__device__ __half g_w2h[(size_t)Ee * Dd * Hh];
__device__ int   g_counts[Ee];
__device__ int   g_offsets[Ee + 1];
__device__ int   g_topi[NK];
__device__ float g_topw[NK];
__device__ int   g_pos[NK];
__device__ int   g_slot_tok[NK];
__device__ int   g_tok_slot[NK];
__device__ float g_probsum[Ee];

// ---------------- helpers ----------------------------------------------------
__device__ __forceinline__ void cp16(uint32_t dst, const void* src, int pbytes) {
    asm volatile("cp.async.cg.shared.global [%0], [%1], 16, %2;"
                 :: "r"(dst), "l"(src), "r"(pbytes));
}
__device__ __forceinline__ void mma_f16(float c[4], uint32_t a0, uint32_t a1,
                                        uint32_t a2, uint32_t a3,
                                        uint32_t b0, uint32_t b1) {
    asm volatile(
        "mma.sync.aligned.m16n8k16.row.col.f32.f16.f16.f32 "
        "{%0,%1,%2,%3}, {%4,%5,%6,%7}, {%8,%9}, {%0,%1,%2,%3};"
        : "+f"(c[0]), "+f"(c[1]), "+f"(c[2]), "+f"(c[3])
        : "r"(a0), "r"(a1), "r"(a2), "r"(a3), "r"(b0), "r"(b1));
}
__device__ __forceinline__ void ldsm4(uint32_t a[4], uint32_t addr) {
    asm volatile("ldmatrix.sync.aligned.m8n8.x4.shared.b16 {%0,%1,%2,%3}, [%4];"
                 : "=r"(a[0]), "=r"(a[1]), "=r"(a[2]), "=r"(a[3]) : "r"(addr));
}
__device__ __forceinline__ void ldsm4t(uint32_t a[4], uint32_t addr) {
    asm volatile("ldmatrix.sync.aligned.m8n8.x4.trans.shared.b16 {%0,%1,%2,%3}, [%4];"
                 : "=r"(a[0]), "=r"(a[1]), "=r"(a[2]), "=r"(a[3]) : "r"(addr));
}
__device__ __forceinline__ float gelu_exact(float c) {
    return 0.5f * c * (1.f + erff(c * 0.7071067811865475f));
}

// ---------------- routing ----------------------------------------------------
__global__ void init_kernel() {
    int t = threadIdx.x;
    if (t < Ee) { g_counts[t] = 0; g_probsum[t] = 0.f; }
}

__global__ void routing_kernel(const float* __restrict__ x,
                               const float* __restrict__ Wr) {
    int n = blockIdx.x;
    int t = threadIdx.x;
    const float* xr = x + (size_t)n * Dd;
    float a0 = 0.f, a1 = 0.f, a2 = 0.f;
    for (int d = t; d < Dd; d += 128) {
        float xv = xr[d];
        a0 += xv * Wr[d];
        a1 += xv * Wr[Dd + d];
        a2 += xv * Wr[2 * Dd + d];
    }
    __shared__ float s0[128], s1[128], s2[128];
    s0[t] = a0; s1[t] = a1; s2[t] = a2;
    __syncthreads();
    for (int off = 64; off > 0; off >>= 1) {
        if (t < off) { s0[t] += s0[t+off]; s1[t] += s1[t+off]; s2[t] += s2[t+off]; }
        __syncthreads();
    }
    if (t == 0) {
        float z0 = s0[0], z1 = s1[0], z2 = s2[0];
        const float inv3 = 0.57735026918962576f;
        float logits[Ee];
        #pragma unroll
        for (int e = 0; e < Ee; e++) {
            float d0 = (e & 4) ? 1.f : -1.f;
            float d1 = (e & 2) ? 1.f : -1.f;
            float d2 = (e & 1) ? 1.f : -1.f;
            logits[e] = (d0 * z0 + d1 * z1 + d2 * z2) * inv3;
        }
        float m = logits[0];
        #pragma unroll
        for (int e = 1; e < Ee; e++) m = fmaxf(m, logits[e]);
        float p[Ee]; float sum = 0.f;
        #pragma unroll
        for (int e = 0; e < Ee; e++) { p[e] = expf(logits[e] - m); sum += p[e]; }
        float invs = 1.f / sum;
        #pragma unroll
        for (int e = 0; e < Ee; e++) atomicAdd(&g_probsum[e], p[e] * invs);
        int i0 = 0;
        #pragma unroll
        for (int e = 1; e < Ee; e++) if (p[e] > p[i0]) i0 = e;
        int i1 = (i0 == 0) ? 1 : 0;
        #pragma unroll
        for (int e = 0; e < Ee; e++) if (e != i0 && p[e] > p[i1]) i1 = e;
        float v0 = p[i0], v1 = p[i1];
        float wd = 1.f / (v0 + v1);
        g_topi[n*2]   = i0; g_topi[n*2+1] = i1;
        g_topw[n*2]   = v0 * wd; g_topw[n*2+1] = v1 * wd;
        g_pos[n*2]    = atomicAdd(&g_counts[i0], 1);
        g_pos[n*2+1]  = atomicAdd(&g_counts[i1], 1);
    }
}

__global__ void offsets_kernel() {
    if (threadIdx.x == 0 && blockIdx.x == 0) {
        int s = 0;
        for (int e = 0; e < Ee; e++) { g_offsets[e] = s; s += g_counts[e]; }
        g_offsets[Ee] = s;
    }
}

__global__ void fill_kernel() {
    int idx = blockIdx.x * 256 + threadIdx.x;
    if (idx >= NK) return;
    int e = g_topi[idx];
    int slot = g_offsets[e] + g_pos[idx];
    g_slot_tok[slot] = idx >> 1;
    g_tok_slot[idx]  = slot;
}

// fp32 -> fp16 converters (grid-stride, float4 -> half4)
__global__ void conv_kernel(const float* __restrict__ src, __half* __restrict__ dst,
                            int n4) {
    int i = blockIdx.x * 256 + threadIdx.x;
    int stride = gridDim.x * 256;
    for (; i < n4; i += stride) {
        float4 v = ((const float4*)src)[i];
        __half2* d = (__half2*)(dst + (size_t)i * 4);
        d[0] = __floats2half2_rn(v.x, v.y);
        d[1] = __floats2half2_rn(v.z, v.w);
    }
}

// ---------------- fp16 tensor-core GEMMs ------------------------------------
// Block tile 128x128, BK=32. 8 warps 2(m)x4(n), warp tile 64x32, m16n8k16.
// A smem: 128 rows x 64B (32 halves), swizzle u ^ ((r>>1)&3) on 16B units.
// B smem: 32 rows x 256B (128 halves), swizzle u ^ (k&7) on 16B units.
#define BKT 32
#define A_BY (128*64)             // 8 KB per stage
#define B_BY (32*256)             // 8 KB per stage
#define NST 4
#define GEMM_SMEM (NST*(A_BY+B_BY) + 512)

template<bool G1>
__global__ __launch_bounds__(256, 2) void moe_gemm(const __half* __restrict__ Wglob) {
    constexpr int KTOT = G1 ? Dd : Hh;
    constexpr int NSTR = G1 ? Hh : Dd;
    constexpr int NT = KTOT / BKT;       // 24 / 96

    int e = blockIdx.z;
    int cnt = g_counts[e];
    int m0 = blockIdx.y * 128;
    if (m0 >= cnt) return;
    int n0 = blockIdx.x * 128;
    int base = g_offsets[e] + m0;
    int rows = min(128, cnt - m0);

    extern __shared__ char sm[];
    uint32_t uA = (uint32_t)__cvta_generic_to_shared(sm);
    uint32_t uB = uA + NST * A_BY;
    int* stok = (int*)(sm + NST * (A_BY + B_BY));

    int t = threadIdx.x, wid = t >> 5, lane = t & 31;
    int wm0 = (wid & 1) * 64, wn0 = (wid >> 1) * 32;
    int gid = lane >> 2, tig = lane & 3;

    // ldmatrix lane addressing (A, non-trans): tiles m0-7/m8-15 x k0-7/k8-15
    int la_r = (lane & 7) + ((lane >> 3) & 1) * 8;
    int la_u = (lane >> 4) & 1;
    // ldmatrix lane addressing (B, trans): k rows, n chunks
    int lb_k = ((lane >> 3) & 1) * 8 + (lane & 7);
    int lb_n = ((lane >> 4) & 1) * 8;

    const __half* Wb = Wglob + (size_t)e * Dd * Hh;
    const __half* Ag = G1 ? g_xh : g_hh;

    if (G1 && t < 128) stok[t] = (t < rows) ? g_slot_tok[base + t] : -1;
    __syncthreads();

    auto issue = [&](int kt) {
        int buf = kt & (NST - 1);
        uint32_t ab = uA + buf * A_BY;
        uint32_t bb = uB + buf * B_BY;
        #pragma unroll
        for (int i = 0; i < 2; i++) {                 // A: 512 x 16B chunks
            int idx = i * 256 + t;
            int r = idx >> 2, u = idx & 3;
            uint32_t dst = ab + r * 64 + ((u ^ ((r >> 1) & 3)) << 4);
            if (G1) {
                int tok = stok[r];
                cp16(dst, Ag + (size_t)max(tok, 0) * KTOT + kt * BKT + u * 8,
                     (tok >= 0) ? 16 : 0);
            } else {
                cp16(dst, Ag + (size_t)(base + min(r, rows - 1)) * KTOT + kt * BKT + u * 8,
                     (r < rows) ? 16 : 0);
            }
        }
        #pragma unroll
        for (int i = 0; i < 2; i++) {                 // B: 512 x 16B chunks
            int idx = i * 256 + t;
            int k = idx >> 4, u = idx & 15;
            uint32_t dst = bb + k * 256 + ((u ^ (k & 7)) << 4);
            cp16(dst, Wb + (size_t)(kt * BKT + k) * NSTR + n0 + u * 8, 16);
        }
        asm volatile("cp.async.commit_group;" ::: "memory");
    };

    issue(0); issue(1); issue(2);

    float acc[4][4][4] = {};

    for (int j = 0; j < NT; j++) {
        int buf = j & (NST - 1);
        if (j <= NT - 3)      asm volatile("cp.async.wait_group 2;" ::: "memory");
        else if (j == NT - 2) asm volatile("cp.async.wait_group 1;" ::: "memory");
        else                  asm volatile("cp.async.wait_group 0;" ::: "memory");
        __syncthreads();
        if (j + 3 < NT) issue(j + 3);

        uint32_t ab = uA + buf * A_BY;
        uint32_t bb = uB + buf * B_BY;

        #pragma unroll
        for (int ks = 0; ks < 2; ks++) {
            uint32_t a[4][4];
            #pragma unroll
            for (int mi = 0; mi < 4; mi++) {
                int r = wm0 + mi * 16 + la_r;
                int u = 2 * ks + la_u;
                ldsm4(a[mi], ab + r * 64 + ((u ^ ((r >> 1) & 3)) << 4));
            }
            uint32_t b[2][4];   // each ldsm4t -> {b0,b1} for n and n+8
            #pragma unroll
            for (int half = 0; half < 2; half++) {
                int k = ks * 16 + lb_k;
                int ncol = wn0 + half * 16 + lb_n;
                int u = ncol >> 3;
                ldsm4t(b[half], bb + k * 256 + ((u ^ (k & 7)) << 4));
            }
            #pragma unroll
            for (int mi = 0; mi < 4; mi++)
                #pragma unroll
                for (int ni = 0; ni < 4; ni++)
                    mma_f16(acc[mi][ni], a[mi][0], a[mi][1], a[mi][2], a[mi][3],
                            b[ni >> 1][(ni & 1) * 2], b[ni >> 1][(ni & 1) * 2 + 1]);
        }
    }

    // epilogue
    #pragma unroll
    for (int mi = 0; mi < 4; mi++) {
        int r0 = wm0 + mi * 16 + gid;
        #pragma unroll
        for (int ni = 0; ni < 4; ni++) {
            int c = n0 + wn0 + ni * 8 + tig * 2;
            #pragma unroll
            for (int half = 0; half < 2; half++) {
                int r = r0 + half * 8;
                if (r < rows) {
                    float v0 = acc[mi][ni][half * 2], v1 = acc[mi][ni][half * 2 + 1];
                    if (G1) {
                        *(__half2*)(g_hh + (size_t)(base + r) * Hh + c) =
                            __floats2half2_rn(gelu_exact(v0), gelu_exact(v1));
                    } else {
                        size_t o = (size_t)(base + r) * Dd + c;
                        g_y[o] = v0; g_y[o + 1] = v1;
                    }
                }
            }
        }
    }
}

// ---------------- combine + aux ---------------------------------------------
__global__ void combine_kernel(float* __restrict__ out) {
    int idx = blockIdx.x * 256 + threadIdx.x;
    if (idx >= Nn * (Dd / 4)) return;
    int n = idx / (Dd / 4), q = idx - n * (Dd / 4);
    int s0 = g_tok_slot[n*2], s1 = g_tok_slot[n*2 + 1];
    float w0 = g_topw[n*2], w1 = g_topw[n*2 + 1];
    float4 y0 = *(const float4*)(g_y + (size_t)s0 * Dd + q * 4);
    float4 y1 = *(const float4*)(g_y + (size_t)s1 * Dd + q * 4);
    float4 o;
    o.x = w0 * y0.x + w1 * y1.x;
    o.y = w0 * y0.y + w1 * y1.y;
    o.z = w0 * y0.z + w1 * y1.z;
    o.w = w0 * y0.w + w1 * y1.w;
    *(float4*)(out + (size_t)n * Dd + q * 4) = o;
}

__global__ void aux_kernel(float* __restrict__ out, int out_size) {
    int extra = out_size - Nn * Dd;
    if (extra <= 0) return;
    int i = blockIdx.x * 256 + threadIdx.x;
    if (i >= extra) return;
    float aux = 0.f;
    #pragma unroll
    for (int e = 0; e < Ee; e++) {
        float tpe = g_probsum[e] * (1.0f / (float)Nn);
        float dlt = tpe - 1.0f / (float)Ee;
        aux += dlt * dlt;
    }
    aux = 0.01f * aux / (float)Ee;
    out[Nn * Dd + i] = aux;
}

// ---------------- launch -----------------------------------------------------
extern "C" void kernel_launch(void* const* d_in, const int* in_sizes, int n_in,
                              void* d_out, int out_size) {
    const float* x  = (const float*)d_in[0];
    const float* Wr = (const float*)d_in[1];
    const float* W1 = (const float*)d_in[2];
    const float* W2 = (const float*)d_in[3];
    float* out = (float*)d_out;

    // device addresses of __device__ scratch (symbols are NOT valid host-side)
    __half* w1h; cudaGetSymbolAddress((void**)&w1h, g_w1h);
    __half* w2h; cudaGetSymbolAddress((void**)&w2h, g_w2h);
    __half* xh;  cudaGetSymbolAddress((void**)&xh,  g_xh);

    cudaFuncSetAttribute(moe_gemm<true>,  cudaFuncAttributeMaxDynamicSharedMemorySize, GEMM_SMEM);
    cudaFuncSetAttribute(moe_gemm<false>, cudaFuncAttributeMaxDynamicSharedMemorySize, GEMM_SMEM);

    init_kernel<<<1, 32>>>();
    routing_kernel<<<Nn, 128>>>(x, Wr);
    {
        int wq = (Ee * Dd * Hh) / 4;
        conv_kernel<<<2048, 256>>>(W1, w1h, wq);
        conv_kernel<<<2048, 256>>>(W2, w2h, wq);
        conv_kernel<<<(Nn * Dd / 4 + 255) / 256, 256>>>(x, xh, Nn * Dd / 4);
    }
    offsets_kernel<<<1, 32>>>();
    fill_kernel<<<(NK + 255) / 256, 256>>>();
    moe_gemm<true><<<dim3(Hh / 128, Nn / 128, Ee), 256, GEMM_SMEM>>>(w1h);
    moe_gemm<false><<<dim3(Dd / 128, Nn / 128, Ee), 256, GEMM_SMEM>>>(w2h);
    combine_kernel<<<(Nn * (Dd / 4) + 255) / 256, 256>>>(out);
    aux_kernel<<<16, 256>>>(out, out_size);
}

// round 9
// speedup vs baseline: 7.5193x; 1.0347x over previous
#include <cuda_runtime.h>
#include <cuda_fp16.h>
#include <math.h>
#include <stdint.h>

#define Bb 2
#define Tt 1024
#define Dd 768
#define Hh 3072
#define Ee 8
#define Nn (Bb*Tt)      // 2048 tokens
#define NK (Nn*2)       // 4096 assignments
#define CAP Nn          // slots per expert (worst case all tokens pick it)

// ---------------- scratch (device globals) ----------------------------------
__device__ __half g_hh[(size_t)Ee * CAP * Hh];   // gelu(x@W1), fp16, slot rows
__device__ float  g_y[(size_t)Ee * CAP * Dd];    // h@W2, slot rows
__device__ __half g_xh[(size_t)Nn * Dd];         // fp16 x
__device__ __half g_w1h[(size_t)Ee * Dd * Hh];
__device__ __half g_w2h[(size_t)Ee * Dd * Hh];
__device__ int   g_counts[Ee];
__device__ float g_topw[NK];
__device__ int   g_slot_tok[Ee * CAP];
__device__ int   g_tok_slot[NK];
__device__ float g_probsum[Ee];

// ---------------- helpers ----------------------------------------------------
__device__ __forceinline__ void cp16(uint32_t dst, const void* src, int pbytes) {
    asm volatile("cp.async.cg.shared.global [%0], [%1], 16, %2;"
                 :: "r"(dst), "l"(src), "r"(pbytes));
}
__device__ __forceinline__ void mma_f16(float c[4], uint32_t a0, uint32_t a1,
                                        uint32_t a2, uint32_t a3,
                                        uint32_t b0, uint32_t b1) {
    asm volatile(
        "mma.sync.aligned.m16n8k16.row.col.f32.f16.f16.f32 "
        "{%0,%1,%2,%3}, {%4,%5,%6,%7}, {%8,%9}, {%0,%1,%2,%3};"
        : "+f"(c[0]), "+f"(c[1]), "+f"(c[2]), "+f"(c[3])
        : "r"(a0), "r"(a1), "r"(a2), "r"(a3), "r"(b0), "r"(b1));
}
__device__ __forceinline__ void ldsm4(uint32_t a[4], uint32_t addr) {
    asm volatile("ldmatrix.sync.aligned.m8n8.x4.shared.b16 {%0,%1,%2,%3}, [%4];"
                 : "=r"(a[0]), "=r"(a[1]), "=r"(a[2]), "=r"(a[3]) : "r"(addr));
}
__device__ __forceinline__ void ldsm4t(uint32_t a[4], uint32_t addr) {
    asm volatile("ldmatrix.sync.aligned.m8n8.x4.trans.shared.b16 {%0,%1,%2,%3}, [%4];"
                 : "=r"(a[0]), "=r"(a[1]), "=r"(a[2]), "=r"(a[3]) : "r"(addr));
}
__device__ __forceinline__ float gelu_exact(float c) {
    return 0.5f * c * (1.f + erff(c * 0.7071067811865475f));
}

// ---------------- setup ------------------------------------------------------
__global__ void init_kernel() {
    int t = threadIdx.x;
    if (t < Ee) { g_counts[t] = 0; g_probsum[t] = 0.f; }
}

// routing: also writes the dispatch tables directly (fixed-capacity slots)
__global__ void routing_kernel(const float* __restrict__ x,
                               const float* __restrict__ Wr) {
    int n = blockIdx.x;
    int t = threadIdx.x;
    const float* xr = x + (size_t)n * Dd;
    float a0 = 0.f, a1 = 0.f, a2 = 0.f;
    for (int d = t; d < Dd; d += 128) {
        float xv = xr[d];
        a0 += xv * Wr[d];
        a1 += xv * Wr[Dd + d];
        a2 += xv * Wr[2 * Dd + d];
    }
    __shared__ float s0[128], s1[128], s2[128];
    s0[t] = a0; s1[t] = a1; s2[t] = a2;
    __syncthreads();
    for (int off = 64; off > 0; off >>= 1) {
        if (t < off) { s0[t] += s0[t+off]; s1[t] += s1[t+off]; s2[t] += s2[t+off]; }
        __syncthreads();
    }
    if (t == 0) {
        float z0 = s0[0], z1 = s1[0], z2 = s2[0];
        const float inv3 = 0.57735026918962576f;
        float logits[Ee];
        #pragma unroll
        for (int e = 0; e < Ee; e++) {
            float d0 = (e & 4) ? 1.f : -1.f;
            float d1 = (e & 2) ? 1.f : -1.f;
            float d2 = (e & 1) ? 1.f : -1.f;
            logits[e] = (d0 * z0 + d1 * z1 + d2 * z2) * inv3;
        }
        float m = logits[0];
        #pragma unroll
        for (int e = 1; e < Ee; e++) m = fmaxf(m, logits[e]);
        float p[Ee]; float sum = 0.f;
        #pragma unroll
        for (int e = 0; e < Ee; e++) { p[e] = expf(logits[e] - m); sum += p[e]; }
        float invs = 1.f / sum;
        #pragma unroll
        for (int e = 0; e < Ee; e++) atomicAdd(&g_probsum[e], p[e] * invs);
        int i0 = 0;
        #pragma unroll
        for (int e = 1; e < Ee; e++) if (p[e] > p[i0]) i0 = e;
        int i1 = (i0 == 0) ? 1 : 0;
        #pragma unroll
        for (int e = 0; e < Ee; e++) if (e != i0 && p[e] > p[i1]) i1 = e;
        float v0 = p[i0], v1 = p[i1];
        float wd = 1.f / (v0 + v1);
        g_topw[n*2]   = v0 * wd; g_topw[n*2+1] = v1 * wd;
        int pos0 = atomicAdd(&g_counts[i0], 1);
        int pos1 = atomicAdd(&g_counts[i1], 1);
        int slot0 = i0 * CAP + pos0;
        int slot1 = i1 * CAP + pos1;
        g_slot_tok[slot0] = n;  g_tok_slot[n*2]     = slot0;
        g_slot_tok[slot1] = n;  g_tok_slot[n*2 + 1] = slot1;
    }
}

// one kernel converts W1, W2, x to fp16 (grid-stride over 16B quads)
#define WQ ((Ee*Dd*Hh)/4)
#define XQ ((Nn*Dd)/4)
__global__ void conv_all_kernel(const float* __restrict__ W1,
                                const float* __restrict__ W2,
                                const float* __restrict__ x) {
    __half* w1h = g_w1h;
    __half* w2h = g_w2h;
    __half* xh  = g_xh;
    long long i = blockIdx.x * 256ll + threadIdx.x;
    long long stride = gridDim.x * 256ll;
    long long total = 2ll * WQ + XQ;
    for (; i < total; i += stride) {
        const float* s; __half* d; long long q;
        if (i < WQ)            { s = W1; d = w1h; q = i; }
        else if (i < 2ll * WQ) { s = W2; d = w2h; q = i - WQ; }
        else                   { s = x;  d = xh;  q = i - 2ll * WQ; }
        float4 v = ((const float4*)s)[q];
        __half2* dd = (__half2*)(d + q * 4);
        dd[0] = __floats2half2_rn(v.x, v.y);
        dd[1] = __floats2half2_rn(v.z, v.w);
    }
}

// ---------------- fp16 tensor-core GEMMs ------------------------------------
#define BKT 32
#define A_BY (128*64)             // 8 KB per stage
#define B_BY (32*256)             // 8 KB per stage
#define NST 4
#define GEMM_SMEM (NST*(A_BY+B_BY) + 512)

template<bool G1>
__global__ __launch_bounds__(256, 2) void moe_gemm(const __half* __restrict__ Wglob) {
    constexpr int KTOT = G1 ? Dd : Hh;
    constexpr int NSTR = G1 ? Hh : Dd;
    constexpr int NT = KTOT / BKT;       // 24 / 96

    int e = blockIdx.z;
    int cnt = g_counts[e];
    int m0 = blockIdx.y * 128;
    if (m0 >= cnt) return;
    int n0 = blockIdx.x * 128;
    int base = e * CAP + m0;
    int rows = min(128, cnt - m0);

    extern __shared__ char sm[];
    uint32_t uA = (uint32_t)__cvta_generic_to_shared(sm);
    uint32_t uB = uA + NST * A_BY;
    int* stok = (int*)(sm + NST * (A_BY + B_BY));

    int t = threadIdx.x, wid = t >> 5, lane = t & 31;
    int wm0 = (wid & 1) * 64, wn0 = (wid >> 1) * 32;
    int gid = lane >> 2, tig = lane & 3;

    int la_r = (lane & 7) + ((lane >> 3) & 1) * 8;
    int la_u = (lane >> 4) & 1;
    int lb_k = ((lane >> 3) & 1) * 8 + (lane & 7);
    int lb_n = ((lane >> 4) & 1) * 8;

    const __half* Wb = Wglob + (size_t)e * Dd * Hh;
    const __half* Ag = G1 ? g_xh : g_hh;

    if (G1 && t < 128) stok[t] = (t < rows) ? g_slot_tok[base + t] : -1;
    __syncthreads();

    auto issue = [&](int kt) {
        int buf = kt & (NST - 1);
        uint32_t ab = uA + buf * A_BY;
        uint32_t bb = uB + buf * B_BY;
        #pragma unroll
        for (int i = 0; i < 2; i++) {                 // A: 512 x 16B chunks
            int idx = i * 256 + t;
            int r = idx >> 2, u = idx & 3;
            uint32_t dst = ab + r * 64 + ((u ^ ((r >> 1) & 3)) << 4);
            if (G1) {
                int tok = stok[r];
                cp16(dst, Ag + (size_t)max(tok, 0) * KTOT + kt * BKT + u * 8,
                     (tok >= 0) ? 16 : 0);
            } else {
                cp16(dst, Ag + (size_t)(base + min(r, rows - 1)) * KTOT + kt * BKT + u * 8,
                     (r < rows) ? 16 : 0);
            }
        }
        #pragma unroll
        for (int i = 0; i < 2; i++) {                 // B: 512 x 16B chunks
            int idx = i * 256 + t;
            int k = idx >> 4, u = idx & 15;
            uint32_t dst = bb + k * 256 + ((u ^ (k & 7)) << 4);
            cp16(dst, Wb + (size_t)(kt * BKT + k) * NSTR + n0 + u * 8, 16);
        }
        asm volatile("cp.async.commit_group;" ::: "memory");
    };

    issue(0); issue(1); issue(2);

    float acc[4][4][4] = {};

    for (int j = 0; j < NT; j++) {
        int buf = j & (NST - 1);
        if (j <= NT - 3)      asm volatile("cp.async.wait_group 2;" ::: "memory");
        else if (j == NT - 2) asm volatile("cp.async.wait_group 1;" ::: "memory");
        else                  asm volatile("cp.async.wait_group 0;" ::: "memory");
        __syncthreads();
        if (j + 3 < NT) issue(j + 3);

        uint32_t ab = uA + buf * A_BY;
        uint32_t bb = uB + buf * B_BY;

        #pragma unroll
        for (int ks = 0; ks < 2; ks++) {
            uint32_t a[4][4];
            #pragma unroll
            for (int mi = 0; mi < 4; mi++) {
                int r = wm0 + mi * 16 + la_r;
                int u = 2 * ks + la_u;
                ldsm4(a[mi], ab + r * 64 + ((u ^ ((r >> 1) & 3)) << 4));
            }
            uint32_t b[2][4];
            #pragma unroll
            for (int half = 0; half < 2; half++) {
                int k = ks * 16 + lb_k;
                int ncol = wn0 + half * 16 + lb_n;
                int u = ncol >> 3;
                ldsm4t(b[half], bb + k * 256 + ((u ^ (k & 7)) << 4));
            }
            #pragma unroll
            for (int mi = 0; mi < 4; mi++)
                #pragma unroll
                for (int ni = 0; ni < 4; ni++)
                    mma_f16(acc[mi][ni], a[mi][0], a[mi][1], a[mi][2], a[mi][3],
                            b[ni >> 1][(ni & 1) * 2], b[ni >> 1][(ni & 1) * 2 + 1]);
        }
    }

    // epilogue
    #pragma unroll
    for (int mi = 0; mi < 4; mi++) {
        int r0 = wm0 + mi * 16 + gid;
        #pragma unroll
        for (int ni = 0; ni < 4; ni++) {
            int c = n0 + wn0 + ni * 8 + tig * 2;
            #pragma unroll
            for (int half = 0; half < 2; half++) {
                int r = r0 + half * 8;
                if (r < rows) {
                    float v0 = acc[mi][ni][half * 2], v1 = acc[mi][ni][half * 2 + 1];
                    if (G1) {
                        *(__half2*)(g_hh + (size_t)(base + r) * Hh + c) =
                            __floats2half2_rn(gelu_exact(v0), gelu_exact(v1));
                    } else {
                        size_t o = (size_t)(base + r) * Dd + c;
                        g_y[o] = v0; g_y[o + 1] = v1;
                    }
                }
            }
        }
    }
}

// ---------------- combine (+fused aux) ---------------------------------------
__global__ void combine_kernel(float* __restrict__ out, int out_size) {
    int idx = blockIdx.x * 256 + threadIdx.x;
    if (idx < Nn * (Dd / 4)) {
        int n = idx / (Dd / 4), q = idx - n * (Dd / 4);
        int s0 = g_tok_slot[n*2], s1 = g_tok_slot[n*2 + 1];
        float w0 = g_topw[n*2], w1 = g_topw[n*2 + 1];
        float4 y0 = *(const float4*)(g_y + (size_t)s0 * Dd + q * 4);
        float4 y1 = *(const float4*)(g_y + (size_t)s1 * Dd + q * 4);
        float4 o;
        o.x = w0 * y0.x + w1 * y1.x;
        o.y = w0 * y0.y + w1 * y1.y;
        o.z = w0 * y0.z + w1 * y1.z;
        o.w = w0 * y0.w + w1 * y1.w;
        *(float4*)(out + (size_t)n * Dd + q * 4) = o;
    }
    if (blockIdx.x == 0 && threadIdx.x == 0) {
        int extra = out_size - Nn * Dd;
        if (extra > 0) {
            float aux = 0.f;
            #pragma unroll
            for (int e = 0; e < Ee; e++) {
                float tpe = g_probsum[e] * (1.0f / (float)Nn);
                float dlt = tpe - 1.0f / (float)Ee;
                aux += dlt * dlt;
            }
            aux = 0.01f * aux / (float)Ee;
            for (int i = 0; i < extra; i++) out[Nn * Dd + i] = aux;
        }
    }
}

// ---------------- launch -----------------------------------------------------
extern "C" void kernel_launch(void* const* d_in, const int* in_sizes, int n_in,
                              void* d_out, int out_size) {
    const float* x  = (const float*)d_in[0];
    const float* Wr = (const float*)d_in[1];
    const float* W1 = (const float*)d_in[2];
    const float* W2 = (const float*)d_in[3];
    float* out = (float*)d_out;

    cudaFuncSetAttribute(moe_gemm<true>,  cudaFuncAttributeMaxDynamicSharedMemorySize, GEMM_SMEM);
    cudaFuncSetAttribute(moe_gemm<false>, cudaFuncAttributeMaxDynamicSharedMemorySize, GEMM_SMEM);

    __half* w1h; cudaGetSymbolAddress((void**)&w1h, g_w1h);
    __half* w2h; cudaGetSymbolAddress((void**)&w2h, g_w2h);

    init_kernel<<<1, 32>>>();
    routing_kernel<<<Nn, 128>>>(x, Wr);
    conv_all_kernel<<<4096, 256>>>(W1, W2, x);
    moe_gemm<true><<<dim3(Hh / 128, Nn / 128, Ee), 256, GEMM_SMEM>>>(w1h);
    moe_gemm<false><<<dim3(Dd / 128, Nn / 128, Ee), 256, GEMM_SMEM>>>(w2h);
    combine_kernel<<<(Nn * (Dd / 4) + 255) / 256, 256>>>(out, out_size);
}